// round 14
// baseline (speedup 1.0000x reference)
#include <cuda_runtime.h>
#include <cuda_fp16.h>
#include <cstdint>

// Problem constants (fixed by the dataset)
#define VOCAB  10000
#define DD     512
#define NL     4
#define BB     32
#define SS     1024
#define M_TOT  (BB * SS)     // 32768
#define N_TOT  (3 * DD)      // 1536
#define K_TOT  DD            // 512

// ---------------------------------------------------------------------------
// Scratch (device globals — allocation-free per harness rules)
// ---------------------------------------------------------------------------
__device__ __half        g_U16[(size_t)M_TOT * N_TOT];        // 100 MB, one layer's U (fp16)
__device__ __half        g_x16[2][(size_t)M_TOT * DD];        // fp16 x, ping-pong
__device__ __half        g_W16[(size_t)NL * N_TOT * K_TOT];   // W^T fp16  [l][n][k]
__device__ unsigned int  g_padbits[BB][SS / 32];              // bit s%32 of word s/32: pad at (b,s)
__device__ int           g_prog[NL][256];                     // GEMM m-tile completion (0..12)
__device__ int           g_sprog[NL][64];                     // scan 16-step-block completion (0..512)
__device__ int           g_ticket;                            // GEMM work ticket

// ---------------------------------------------------------------------------
// PTX helpers (sm_80-level; compiles for plain sm_100)
// ---------------------------------------------------------------------------
__device__ __forceinline__ uint32_t smem_u32(const void* p) {
    uint32_t a;
    asm("{ .reg .u64 t; cvta.to.shared.u64 t, %1; cvt.u32.u64 %0, t; }" : "=r"(a) : "l"(p));
    return a;
}
__device__ __forceinline__ void cpa16(uint32_t dst, const void* src) {
    asm volatile("cp.async.cg.shared.global [%0], [%1], 16;" :: "r"(dst), "l"(src));
}
__device__ __forceinline__ void cp_commit() {
    asm volatile("cp.async.commit_group;" ::: "memory");
}
template <int N> __device__ __forceinline__ void cp_wait() {
    asm volatile("cp.async.wait_group %0;" :: "n"(N) : "memory");
}
__device__ __forceinline__ void ldm4(uint32_t* r, uint32_t addr) {
    asm volatile("ldmatrix.sync.aligned.m8n8.x4.shared.b16 {%0,%1,%2,%3}, [%4];"
                 : "=r"(r[0]), "=r"(r[1]), "=r"(r[2]), "=r"(r[3]) : "r"(addr));
}
__device__ __forceinline__ void mma16816(float* d, const uint32_t* a, const uint32_t* b) {
    asm volatile("mma.sync.aligned.m16n8k16.row.col.f32.f16.f16.f32 "
                 "{%0,%1,%2,%3}, {%4,%5,%6,%7}, {%8,%9}, {%0,%1,%2,%3};"
                 : "+f"(d[0]), "+f"(d[1]), "+f"(d[2]), "+f"(d[3])
                 : "r"(a[0]), "r"(a[1]), "r"(a[2]), "r"(a[3]), "r"(b[0]), "r"(b[1]));
}
__device__ __forceinline__ float htanh(float z) {
    float r;
    asm("tanh.approx.f32 %0, %1;" : "=f"(r) : "f"(z));
    return r;
}
__device__ __forceinline__ float fast_sigmoid(float z) {
    return fmaf(0.5f, htanh(0.5f * z), 0.5f);    // sigma(z) = 0.5*tanh(z/2)+0.5
}
__device__ __forceinline__ float h2f_raw(unsigned short u) {
    __half_raw r; r.x = u;
    return __half2float((__half)r);
}

// ---------------------------------------------------------------------------
// Persistent kernel: CTAs [0,64) scan all 4 layers; CTAs [64,296) are GEMM
// workers pulling (layer, mtile, ntile) tickets (layer-major, m-major).
// Sync protocol:
//   g_prog[l][mt]  = completed n-tiles of GEMM l, m-tile mt (scan l gates @12)
//   g_sprog[l][blk]= scan-l warp arrivals per 16-step block (GEMM l+1 gates @512)
// Buffer reuse (x16 ping-pong, shared U16) is ordered by this chain itself.
// ---------------------------------------------------------------------------
#define BM 128
#define BN 128
#define BK 64
#define AS_BYTES    (BM * BK * 2)               // 16384
#define BS_BYTES    (BN * BK * 2)               // 16384
#define STAGE_BYTES (AS_BYTES + BS_BYTES)       // 32768
#define LAYER_SMEM  (3 * STAGE_BYTES)           // 98304 (GEMM path; scan uses 64KB)
#define SCAN_CTAS   64
#define GRID_CTAS   296                         // 2 per SM x 148 SMs
#define SLOTS       32                          // scan ring: 32 slots x 256B per warp
#define TILES_PER_L 3072                        // 256 mt x 12 nt

__global__ __launch_bounds__(256, 2) void sru_persist_kernel(const float* __restrict__ vall,
                                                             const float* __restrict__ ball,
                                                             float* __restrict__ dout) {
    extern __shared__ __align__(16) unsigned char smem_raw[];
    const int tid = threadIdx.x, lane = tid & 31, wid = tid >> 5;

    if (blockIdx.x >= SCAN_CTAS) {
        // ===================== GEMM worker =====================
        const uint32_t sb = smem_u32(smem_raw);
        const int wm = wid >> 2, wn = wid & 3;
        const int grp = lane >> 3, l8 = lane & 7;
        const int a_r  = ((grp & 1) << 3) + l8;
        const int a_kh = grp >> 1;
        const int b_r  = ((grp >> 1) << 3) + l8;
        const int b_kh = grp & 1;
        uint32_t swa[4], swb[4];
#pragma unroll
        for (int ks = 0; ks < 4; ++ks) {
            swa[ks] = (uint32_t)((ks * 32 + a_kh * 16) ^ ((a_r & 7) * 16));
            swb[ks] = (uint32_t)((ks * 32 + b_kh * 16) ^ ((b_r & 7) * 16));
        }
        const uint32_t a_row_base = (uint32_t)((wm * 64 + a_r) * 128);
        const uint32_t b_row_base = (uint32_t)((wn * 32 + b_r) * 128);

        __shared__ int s_tk;
        for (;;) {
            if (tid == 0) s_tk = atomicAdd(&g_ticket, 1);
            __syncthreads();
            const int tk = s_tk;
            __syncthreads();
            if (tk >= NL * TILES_PER_L) break;
            const int l  = tk / TILES_PER_L;
            const int r_ = tk - l * TILES_PER_L;
            const int mt = r_ / 12, nt = r_ - mt * 12;
            const int m0 = mt * BM, n0 = nt * BN;
            const int xin = l & 1;

            // Gate on scan l-1 having produced x rows for this m-tile.
            if (l > 0) {
                if (tid == 0) {
                    volatile const int* p = (volatile const int*)&g_sprog[l - 1][mt >> 2];
                    int it = 0;
                    while (*p != 512 && it < (1 << 18)) { __nanosleep(200); ++it; }
                }
                __syncthreads();
            }

            const __half* __restrict__ A  = g_x16[xin] + (size_t)m0 * K_TOT;
            const __half* __restrict__ Bm = g_W16 + (size_t)l * N_TOT * K_TOT + (size_t)n0 * K_TOT;

            auto load_chunk = [&](int stage, int kc) {
                const uint32_t ab = sb + stage * STAGE_BYTES;
                const uint32_t bb = ab + AS_BYTES;
#pragma unroll
                for (int i = 0; i < 4; ++i) {
                    const int j = tid + i * 256;
                    const int rr = j >> 3, seg = j & 7;
                    const uint32_t soff = (uint32_t)(rr * 128 + ((seg * 16) ^ ((rr & 7) * 16)));
                    const size_t go = (size_t)rr * K_TOT + kc * 64 + seg * 8;
                    cpa16(ab + soff, A + go);
                    cpa16(bb + soff, Bm + go);
                }
                cp_commit();
            };

            float acc[4][4][4];
#pragma unroll
            for (int mi = 0; mi < 4; ++mi)
#pragma unroll
                for (int ni = 0; ni < 4; ++ni)
#pragma unroll
                    for (int q = 0; q < 4; ++q) acc[mi][ni][q] = 0.0f;

            load_chunk(0, 0);
            load_chunk(1, 1);

#pragma unroll
            for (int c = 0; c < 8; ++c) {
                if (c < 7) cp_wait<1>(); else cp_wait<0>();
                __syncthreads();
                if (c + 2 < 8) load_chunk((c + 2) % 3, c + 2);

                const uint32_t ab = sb + (c % 3) * STAGE_BYTES;
                const uint32_t bb = ab + AS_BYTES;
                const uint32_t abase = ab + a_row_base;
                const uint32_t bbase = bb + b_row_base;
#pragma unroll
                for (int ks = 0; ks < 4; ++ks) {
                    uint32_t areg[4][4], breg[2][4];
#pragma unroll
                    for (int nq = 0; nq < 2; ++nq) ldm4(breg[nq], bbase + nq * 2048 + swb[ks]);
#pragma unroll
                    for (int mi = 0; mi < 4; ++mi) ldm4(areg[mi], abase + mi * 2048 + swa[ks]);
#pragma unroll
                    for (int mi = 0; mi < 4; ++mi)
#pragma unroll
                        for (int ni = 0; ni < 4; ++ni)
                            mma16816(acc[mi][ni], areg[mi], &breg[ni >> 1][(ni & 1) * 2]);
                }
            }

            const int er = lane >> 2, ec = (lane & 3) * 2;
            __half* __restrict__ Uo = g_U16 + (size_t)m0 * N_TOT + n0;
#pragma unroll
            for (int mi = 0; mi < 4; ++mi) {
#pragma unroll
                for (int ni = 0; ni < 4; ++ni) {
                    const int m = wm * 64 + mi * 16 + er;
                    const int n = wn * 32 + ni * 8 + ec;
                    const __half2 v0 = __floats2half2_rn(acc[mi][ni][0], acc[mi][ni][1]);
                    const __half2 v1 = __floats2half2_rn(acc[mi][ni][2], acc[mi][ni][3]);
                    *(__half2*)&Uo[(size_t)m * N_TOT + n]       = v0;
                    *(__half2*)&Uo[(size_t)(m + 8) * N_TOT + n] = v1;
                }
            }
            __threadfence();
            __syncthreads();
            if (tid == 0) atomicAdd(&g_prog[l][mt], 1);
        }

    } else {
        // ===================== scan CTA: all 4 layers =====================
        const int t = blockIdx.x * 256 + tid;           // 0..16383
        const int d = t & (DD - 1);
        const int b = t >> 9;
        const int d0 = d & ~31;

        const uint32_t ringbase = smem_u32(smem_raw) + (uint32_t)(wid * SLOTS * 256);
        const int role = lane >> 2, li = lane & 3;      // lanes 0-15 fetch
        const bool fet = (lane < 16);
        const uint32_t soff = (uint32_t)(lane * 16);

        for (int l = 0; l < NL; ++l) {
            const int xin = l & 1;
            const int last = (l == NL - 1);
            const __half* __restrict__ U = g_U16;
            const __half* __restrict__ x16 = g_x16[xin];
            __half* __restrict__ o16 = g_x16[xin ^ 1];

            const float vf = vall[l * 1024 + d];
            const float vr = vall[l * 1024 + 512 + d];
            const float bf = ball[l * 1024 + d];
            const float br = ball[l * 1024 + 512 + d];

            auto wait_tile = [&](int mt2) {
                if (lane == 0) {
                    volatile const int* p = (volatile const int*)&g_prog[l][mt2];
                    int it = 0;
                    while (*p != 12 && it < (1 << 17)) { __nanosleep(100); ++it; }
                }
                __syncwarp();
            };

            auto issue4 = [&](int s) {
                if (fet) {
#pragma unroll
                    for (int i = 0; i < 4; ++i) {
                        const int row = (s + i) * BB + b;
                        const uint32_t dst = ringbase + ((uint32_t)((s + i) & (SLOTS - 1)) << 8) + soff;
                        const void* src = (role < 3)
                            ? (const void*)(U + (size_t)row * N_TOT + role * 512 + d0 + li * 8)
                            : (const void*)(x16 + (size_t)row * DD + d0 + li * 8);
                        cpa16(dst, src);
                    }
                }
                cp_commit();
            };

            float c = 0.0f;

            auto do4 = [&](int s0) {
                const unsigned int pw = g_padbits[b][s0 >> 5] >> (s0 & 31);
#pragma unroll
                for (int k = 0; k < 4; ++k) {
                    const int s = s0 + k;
                    const uint32_t sb_ = ringbase + ((uint32_t)(s & (SLOTS - 1)) << 8);
                    unsigned short hu0, huf, hur, hx;
                    asm volatile("ld.shared.u16 %0, [%1];" : "=h"(hu0) : "r"(sb_ + lane * 2));
                    asm volatile("ld.shared.u16 %0, [%1];" : "=h"(huf) : "r"(sb_ + 64 + lane * 2));
                    asm volatile("ld.shared.u16 %0, [%1];" : "=h"(hur) : "r"(sb_ + 128 + lane * 2));
                    asm volatile("ld.shared.u16 %0, [%1];" : "=h"(hx)  : "r"(sb_ + 192 + lane * 2));
                    const float u0_ = h2f_raw(hu0);
                    const float uf_ = h2f_raw(huf);
                    const float ur_ = h2f_raw(hur);
                    const float x_  = h2f_raw(hx);

                    const int pd = (pw >> k) & 1;
                    const float f = fast_sigmoid(fmaf(vf, c, uf_ + bf));
                    const float r = fast_sigmoid(fmaf(vr, c, ur_ + br));
                    float cn = fmaf(f, c - u0_, u0_);
                    cn = pd ? c : cn;
                    float h = fmaf(r, htanh(cn) - x_, x_);
                    h = pd ? 0.0f : h;
                    c = cn;

                    const int row = s * BB + b;
                    if (!last) o16[(size_t)row * DD + d] = __float2half_rn(h);
                    else       dout[((size_t)b * SS + s) * DD + d] = h;
                }
                // Release h rows to layer l+1 GEMM per 16-step block.
                if (!last && (s0 & 12) == 12) {
                    __threadfence();
                    __syncwarp();
                    if (lane == 0) atomicAdd(&g_sprog[l][s0 >> 4], 1);
                }
            };

            for (int g2 = 0; g2 < SLOTS / 4; ++g2) {
                wait_tile(g2);
                issue4(g2 * 4);
            }
            for (int s0 = 0; s0 < SS - SLOTS; s0 += 4) {
                cp_wait<7>();
                __syncwarp();
                do4(s0);
                wait_tile((s0 + SLOTS) >> 2);
                issue4(s0 + SLOTS);
            }
            cp_wait<0>();
            __syncwarp();
            for (int s0 = SS - SLOTS; s0 < SS; s0 += 4) do4(s0);
        }
    }
}

// ---------------------------------------------------------------------------
// Fused prep: blocks [0, 3072) transpose W -> W16; blocks [3072, 7168) embed.
// ---------------------------------------------------------------------------
__global__ __launch_bounds__(1024) void sru_prep_fused(const float* __restrict__ W,
                                                       const int* __restrict__ ids,
                                                       const float* __restrict__ emb) {
    if (blockIdx.x < 3072) {
        __shared__ float tile[32][33];
        const int id = blockIdx.x;
        const int l   = id / 768;
        const int rem = id - l * 768;
        const int n0  = (rem >> 4) * 32;
        const int k0  = (rem & 15) * 32;
        const int tx = threadIdx.x & 31, ty = threadIdx.x >> 5;
        tile[ty][tx] = __ldg(W + (size_t)l * K_TOT * N_TOT + (size_t)(k0 + ty) * N_TOT + n0 + tx);
        __syncthreads();
        g_W16[(size_t)l * N_TOT * K_TOT + (size_t)(n0 + ty) * K_TOT + k0 + tx] =
            __float2half_rn(tile[tx][ty]);
    } else {
        const int idx = (blockIdx.x - 3072) * 1024 + threadIdx.x;
        const int m = idx >> 7, q = idx & 127;
        const int b = m & 31, s = m >> 5;                           // m = s*32 + b
        const int id = __ldg(ids + b * SS + s);
        const float4 e = *(const float4*)(emb + (size_t)id * DD + q * 4);
        union { __half v[4]; uint2 u; } hh;
        hh.v[0] = __float2half_rn(e.x);
        hh.v[1] = __float2half_rn(e.y);
        hh.v[2] = __float2half_rn(e.z);
        hh.v[3] = __float2half_rn(e.w);
        *(uint2*)(g_x16[0] + (size_t)m * DD + q * 4) = hh.u;
    }
}

// Mask dtype auto-detect + pad bitmask; zeroes all progress state each call.
__global__ void sru_prepmask_kernel(const void* __restrict__ mraw) {
    __shared__ int f_not01, f_notf;
    const int tid = threadIdx.x;
    if (tid == 0) { f_not01 = 0; f_notf = 0; g_ticket = 0; }
    ((int*)g_prog)[tid] = 0;                           // 1024 = NL*256
    if (tid < NL * 64) ((int*)g_sprog)[tid] = 0;       // 256
    __syncthreads();
    const unsigned int* w = (const unsigned int*)mraw;
    int a = 0, fl = 0;
    for (int i = tid; i < M_TOT / 4; i += 1024) {
        const unsigned int x = w[i];
        if (x > 1u) a = 1;
        if (x != 0u && x != 0x3F800000u) fl = 1;
    }
    if (a)  atomicExch(&f_not01, 1);
    if (fl) atomicExch(&f_notf, 1);
    __syncthreads();
    const int mode = (!f_not01) ? 0 : ((!f_notf) ? 1 : 2);
    const int b = tid >> 5, wrd = tid & 31;
    unsigned int bits = 0;
#pragma unroll 4
    for (int i = 0; i < 32; ++i) {
        const int s = wrd * 32 + i;
        const int j = b * SS + s;                      // mask is [B][S]
        int mv;
        if (mode == 0)      mv = ((const int*)mraw)[j] != 0;
        else if (mode == 1) mv = ((const unsigned int*)mraw)[j] != 0u;
        else                mv = ((const unsigned char*)mraw)[j] != 0;
        if (!mv) bits |= (1u << i);
    }
    g_padbits[b][wrd] = bits;
}

// ---------------------------------------------------------------------------
// Launch: prepmask(0), prep_fused(1), one persistent kernel for all layers(2).
// ---------------------------------------------------------------------------
extern "C" void kernel_launch(void* const* d_in, const int* in_sizes, int n_in,
                              void* d_out, int out_size) {
    const int*   ids  = (const int*)d_in[0];
    const void*  mask = d_in[1];
    const float* emb  = (const float*)d_in[2];
    const float* W    = (const float*)d_in[3];
    const float* v    = (const float*)d_in[4];
    const float* bias = (const float*)d_in[5];
    float* out = (float*)d_out;

    cudaFuncSetAttribute(sru_persist_kernel, cudaFuncAttributeMaxDynamicSharedMemorySize, LAYER_SMEM);

    sru_prepmask_kernel<<<1, 1024>>>(mask);                                 // 0
    sru_prep_fused<<<7168, 1024>>>(W, ids, emb);                            // 1
    sru_persist_kernel<<<GRID_CTAS, 256, LAYER_SMEM>>>(v, bias, out);       // 2
}

// round 15
// speedup vs baseline: 1.4517x; 1.4517x over previous
#include <cuda_runtime.h>
#include <cuda_fp16.h>
#include <cstdint>

// Problem constants (fixed by the dataset)
#define VOCAB  10000
#define DD     512
#define NL     4
#define BB     32
#define SS     1024
#define M_TOT  (BB * SS)     // 32768
#define N_TOT  (3 * DD)      // 1536
#define K_TOT  DD            // 512

// ---------------------------------------------------------------------------
// Scratch (device globals — allocation-free per harness rules)
// ---------------------------------------------------------------------------
__device__ __half        g_U16[(size_t)M_TOT * N_TOT];        // 100 MB, one layer's U (fp16)
__device__ __half        g_x16[2][(size_t)M_TOT * DD];        // fp16 x, ping-pong
__device__ __half        g_W16[(size_t)NL * N_TOT * K_TOT];   // W^T fp16  [l][n][k]
__device__ unsigned int  g_padbits[BB][SS / 32];              // bit s%32 of word s/32: pad at (b,s)
__device__ int           g_prog[NL][256];                     // per-layer m-tile completion (0..12)

// ---------------------------------------------------------------------------
// PTX helpers (sm_80-level; compiles for plain sm_100)
// ---------------------------------------------------------------------------
__device__ __forceinline__ uint32_t smem_u32(const void* p) {
    uint32_t a;
    asm("{ .reg .u64 t; cvta.to.shared.u64 t, %1; cvt.u32.u64 %0, t; }" : "=r"(a) : "l"(p));
    return a;
}
__device__ __forceinline__ void cpa16(uint32_t dst, const void* src) {
    asm volatile("cp.async.cg.shared.global [%0], [%1], 16;" :: "r"(dst), "l"(src));
}
__device__ __forceinline__ void cp_commit() {
    asm volatile("cp.async.commit_group;" ::: "memory");
}
template <int N> __device__ __forceinline__ void cp_wait() {
    asm volatile("cp.async.wait_group %0;" :: "n"(N) : "memory");
}
__device__ __forceinline__ void ldm4(uint32_t* r, uint32_t addr) {
    asm volatile("ldmatrix.sync.aligned.m8n8.x4.shared.b16 {%0,%1,%2,%3}, [%4];"
                 : "=r"(r[0]), "=r"(r[1]), "=r"(r[2]), "=r"(r[3]) : "r"(addr));
}
__device__ __forceinline__ void mma16816(float* d, const uint32_t* a, const uint32_t* b) {
    asm volatile("mma.sync.aligned.m16n8k16.row.col.f32.f16.f16.f32 "
                 "{%0,%1,%2,%3}, {%4,%5,%6,%7}, {%8,%9}, {%0,%1,%2,%3};"
                 : "+f"(d[0]), "+f"(d[1]), "+f"(d[2]), "+f"(d[3])
                 : "r"(a[0]), "r"(a[1]), "r"(a[2]), "r"(a[3]), "r"(b[0]), "r"(b[1]));
}
__device__ __forceinline__ float htanh(float z) {
    float r;
    asm("tanh.approx.f32 %0, %1;" : "=f"(r) : "f"(z));
    return r;
}
__device__ __forceinline__ float fast_sigmoid(float z) {
    return fmaf(0.5f, htanh(0.5f * z), 0.5f);    // sigma(z) = 0.5*tanh(z/2)+0.5
}
__device__ __forceinline__ float h2f_raw(unsigned short u) {
    __half_raw r; r.x = u;
    return __half2float((__half)r);
}

// ---------------------------------------------------------------------------
// Fused layer kernel (R13 structure — proven 898.9us):
//   CTAs [0,64)    = SRU scan (8 autonomous warps, 256 lanes)
//   CTAs [64,3136) = GEMM tiles, bid m-major (12 n-tiles per m-tile)
// GEMM publishes m-tile completion in g_prog[layer][mt]; scan warps gate each
// 4-step prefetch group (== exactly one 128-row m-tile) on prog[mt]==12.
// ---------------------------------------------------------------------------
#define BM 128
#define BN 128
#define BK 64
#define AS_BYTES    (BM * BK * 2)               // 16384
#define BS_BYTES    (BN * BK * 2)               // 16384
#define STAGE_BYTES (AS_BYTES + BS_BYTES)       // 32768
#define LAYER_SMEM  (3 * STAGE_BYTES)           // 98304 (GEMM path; scan uses 64KB)
#define SCAN_CTAS   64
#define SLOTS       32                          // scan ring: 32 slots x 256B per warp

__global__ __launch_bounds__(256, 2) void sru_layer_kernel(int layer, int xin,
                                                           const float* __restrict__ vall,
                                                           const float* __restrict__ ball,
                                                           float* __restrict__ dout, int last) {
    extern __shared__ __align__(16) unsigned char smem_raw[];
    const int tid = threadIdx.x, lane = tid & 31, wid = tid >> 5;

    if (blockIdx.x >= SCAN_CTAS) {
        // ===================== GEMM path =====================
        const uint32_t sb = smem_u32(smem_raw);
        const int g  = blockIdx.x - SCAN_CTAS;
        const int mt = g / 12, nt = g - mt * 12;     // m-major: early m-tiles first
        const int m0 = mt * BM, n0 = nt * BN;

        const __half* __restrict__ A  = g_x16[xin] + (size_t)m0 * K_TOT;
        const __half* __restrict__ Bm = g_W16 + (size_t)layer * N_TOT * K_TOT + (size_t)n0 * K_TOT;

        auto load_chunk = [&](int stage, int kc) {
            const uint32_t ab = sb + stage * STAGE_BYTES;
            const uint32_t bb = ab + AS_BYTES;
#pragma unroll
            for (int i = 0; i < 4; ++i) {
                const int j = tid + i * 256;             // 0..1023 : (row, 16B-seg)
                const int r = j >> 3, seg = j & 7;
                const uint32_t soff = (uint32_t)(r * 128 + ((seg * 16) ^ ((r & 7) * 16)));
                const size_t go = (size_t)r * K_TOT + kc * 64 + seg * 8;
                cpa16(ab + soff, A + go);
                cpa16(bb + soff, Bm + go);
            }
            cp_commit();
        };

        const int wm = wid >> 2, wn = wid & 3;
        const int grp = lane >> 3, l8 = lane & 7;
        const int a_r  = ((grp & 1) << 3) + l8;
        const int a_kh = grp >> 1;
        const int b_r  = ((grp >> 1) << 3) + l8;
        const int b_kh = grp & 1;

        uint32_t swa[4], swb[4];
#pragma unroll
        for (int ks = 0; ks < 4; ++ks) {
            swa[ks] = (uint32_t)((ks * 32 + a_kh * 16) ^ ((a_r & 7) * 16));
            swb[ks] = (uint32_t)((ks * 32 + b_kh * 16) ^ ((b_r & 7) * 16));
        }
        const uint32_t a_row_base = (uint32_t)((wm * 64 + a_r) * 128);
        const uint32_t b_row_base = (uint32_t)((wn * 32 + b_r) * 128);

        float acc[4][4][4];
#pragma unroll
        for (int mi = 0; mi < 4; ++mi)
#pragma unroll
            for (int ni = 0; ni < 4; ++ni)
#pragma unroll
                for (int q = 0; q < 4; ++q) acc[mi][ni][q] = 0.0f;

        load_chunk(0, 0);
        load_chunk(1, 1);

#pragma unroll
        for (int c = 0; c < 8; ++c) {
            if (c < 7) cp_wait<1>(); else cp_wait<0>();
            __syncthreads();
            if (c + 2 < 8) load_chunk((c + 2) % 3, c + 2);

            const uint32_t ab = sb + (c % 3) * STAGE_BYTES;
            const uint32_t bb = ab + AS_BYTES;
            const uint32_t abase = ab + a_row_base;
            const uint32_t bbase = bb + b_row_base;
#pragma unroll
            for (int ks = 0; ks < 4; ++ks) {
                uint32_t areg[4][4], breg[2][4];
#pragma unroll
                for (int nq = 0; nq < 2; ++nq) ldm4(breg[nq], bbase + nq * 2048 + swb[ks]);
#pragma unroll
                for (int mi = 0; mi < 4; ++mi) ldm4(areg[mi], abase + mi * 2048 + swa[ks]);
#pragma unroll
                for (int mi = 0; mi < 4; ++mi)
#pragma unroll
                    for (int ni = 0; ni < 4; ++ni)
                        mma16816(acc[mi][ni], areg[mi], &breg[ni >> 1][(ni & 1) * 2]);
            }
        }

        // Epilogue: fp16 half2 stores, then publish this m-tile's n-slice.
        const int er = lane >> 2, ec = (lane & 3) * 2;
        __half* __restrict__ Uo = g_U16 + (size_t)m0 * N_TOT + n0;
#pragma unroll
        for (int mi = 0; mi < 4; ++mi) {
#pragma unroll
            for (int ni = 0; ni < 4; ++ni) {
                const int m = wm * 64 + mi * 16 + er;
                const int n = wn * 32 + ni * 8 + ec;
                const __half2 v0 = __floats2half2_rn(acc[mi][ni][0], acc[mi][ni][1]);
                const __half2 v1 = __floats2half2_rn(acc[mi][ni][2], acc[mi][ni][3]);
                *(__half2*)&Uo[(size_t)m * N_TOT + n]       = v0;
                *(__half2*)&Uo[(size_t)(m + 8) * N_TOT + n] = v1;
            }
        }
        __threadfence();
        __syncthreads();
        if (tid == 0) atomicAdd(&g_prog[layer][mt], 1);

    } else {
        // ===================== scan path =====================
        const int t = blockIdx.x * 256 + tid;           // 0..16383
        const int d = t & (DD - 1);
        const int b = t >> 9;
        const int d0 = d & ~31;                         // warp's d base

        const __half* __restrict__ U = g_U16;
        const __half* __restrict__ x16 = g_x16[xin];
        __half* __restrict__ o16 = g_x16[xin ^ 1];

        const uint32_t ringbase = smem_u32(smem_raw) + (uint32_t)(wid * SLOTS * 256);

        const int role = lane >> 2, li = lane & 3;      // lanes 0-15 fetch
        const bool fet = (lane < 16);
        const uint32_t soff = (uint32_t)(lane * 16);

        const float vf = vall[layer * 1024 + d];
        const float vr = vall[layer * 1024 + 512 + d];
        const float bf = ball[layer * 1024 + d];
        const float br = ball[layer * 1024 + 512 + d];

        auto wait_tile = [&](int mt2) {
            if (lane == 0) {
                volatile const int* p = (volatile const int*)&g_prog[layer][mt2];
                int it = 0;
                while (*p != 12 && it < (1 << 17)) { __nanosleep(100); ++it; }
            }
            __syncwarp();
        };

        auto issue4 = [&](int s) {
            if (fet) {
#pragma unroll
                for (int i = 0; i < 4; ++i) {
                    const int row = (s + i) * BB + b;
                    const uint32_t dst = ringbase + ((uint32_t)((s + i) & (SLOTS - 1)) << 8) + soff;
                    const void* src = (role < 3)
                        ? (const void*)(U + (size_t)row * N_TOT + role * 512 + d0 + li * 8)
                        : (const void*)(x16 + (size_t)row * DD + d0 + li * 8);
                    cpa16(dst, src);
                }
            }
            cp_commit();
        };

        float c = 0.0f;

        auto do4 = [&](int s0) {
            const unsigned int pw = g_padbits[b][s0 >> 5] >> (s0 & 31);
#pragma unroll
            for (int k = 0; k < 4; ++k) {
                const int s = s0 + k;
                const uint32_t sb_ = ringbase + ((uint32_t)(s & (SLOTS - 1)) << 8);
                unsigned short hu0, huf, hur, hx;
                asm volatile("ld.shared.u16 %0, [%1];" : "=h"(hu0) : "r"(sb_ + lane * 2));
                asm volatile("ld.shared.u16 %0, [%1];" : "=h"(huf) : "r"(sb_ + 64 + lane * 2));
                asm volatile("ld.shared.u16 %0, [%1];" : "=h"(hur) : "r"(sb_ + 128 + lane * 2));
                asm volatile("ld.shared.u16 %0, [%1];" : "=h"(hx)  : "r"(sb_ + 192 + lane * 2));
                const float u0_ = h2f_raw(hu0);
                const float uf_ = h2f_raw(huf);
                const float ur_ = h2f_raw(hur);
                const float x_  = h2f_raw(hx);

                const int pd = (pw >> k) & 1;
                const float f = fast_sigmoid(fmaf(vf, c, uf_ + bf));
                const float r = fast_sigmoid(fmaf(vr, c, ur_ + br));
                float cn = fmaf(f, c - u0_, u0_);
                cn = pd ? c : cn;
                float h = fmaf(r, htanh(cn) - x_, x_);
                h = pd ? 0.0f : h;
                c = cn;

                const int row = s * BB + b;
                if (!last) o16[(size_t)row * DD + d] = __float2half_rn(h);
                else       dout[((size_t)b * SS + s) * DD + d] = h;
            }
        };

        // Prologue: 8 groups (32 steps) in flight, each gated on its m-tile.
        for (int g2 = 0; g2 < SLOTS / 4; ++g2) {
            wait_tile(g2);
            issue4(g2 * 4);
        }
        // Steady: wait oldest group (28-step lead), consume, gate+refill.
        for (int s0 = 0; s0 < SS - SLOTS; s0 += 4) {
            cp_wait<7>();
            __syncwarp();
            do4(s0);
            wait_tile((s0 + SLOTS) >> 2);
            issue4(s0 + SLOTS);
        }
        cp_wait<0>();
        __syncwarp();
        for (int s0 = SS - SLOTS; s0 < SS; s0 += 4) do4(s0);
    }
}

// ---------------------------------------------------------------------------
// Fused prep: blocks [0,3072) transpose W -> W16; [3072,7168) embed;
// [7168,7200) pad-bitmask (one block per batch row; detection redundant per
// block — removes the old 25us single-block serial prepmask launch).
// Block 7168 additionally zeroes g_prog.
// ---------------------------------------------------------------------------
__global__ __launch_bounds__(1024) void sru_prep_fused(const float* __restrict__ W,
                                                       const int* __restrict__ ids,
                                                       const float* __restrict__ emb,
                                                       const void* __restrict__ mraw) {
    if (blockIdx.x < 3072) {
        __shared__ float tile[32][33];
        const int id = blockIdx.x;
        const int l   = id / 768;
        const int rem = id - l * 768;
        const int n0  = (rem >> 4) * 32;
        const int k0  = (rem & 15) * 32;
        const int tx = threadIdx.x & 31, ty = threadIdx.x >> 5;
        tile[ty][tx] = __ldg(W + (size_t)l * K_TOT * N_TOT + (size_t)(k0 + ty) * N_TOT + n0 + tx);
        __syncthreads();
        g_W16[(size_t)l * N_TOT * K_TOT + (size_t)(n0 + ty) * K_TOT + k0 + tx] =
            __float2half_rn(tile[tx][ty]);
    } else if (blockIdx.x < 7168) {
        const int idx = (blockIdx.x - 3072) * 1024 + threadIdx.x;   // (m, quad of 4)
        const int m = idx >> 7, q = idx & 127;
        const int b = m & 31, s = m >> 5;                           // m = s*32 + b
        const int id = __ldg(ids + b * SS + s);
        const float4 e = *(const float4*)(emb + (size_t)id * DD + q * 4);
        union { __half v[4]; uint2 u; } hh;
        hh.v[0] = __float2half_rn(e.x);
        hh.v[1] = __float2half_rn(e.y);
        hh.v[2] = __float2half_rn(e.z);
        hh.v[3] = __float2half_rn(e.w);
        *(uint2*)(g_x16[0] + (size_t)m * DD + q * 4) = hh.u;
    } else {
        // Pad bitmask for batch row b. Mask dtype auto-detect:
        // int32 {0,1} / float32 {0,1.0f} / packed bytes.
        const int b = blockIdx.x - 7168;
        const int tid = threadIdx.x;
        __shared__ int f_not01, f_notf;
        if (tid == 0) { f_not01 = 0; f_notf = 0; }
        if (b == 0) ((int*)g_prog)[tid] = 0;           // 1024 = NL*256 counters
        __syncthreads();
        const unsigned int* w = (const unsigned int*)mraw;
        int a = 0, fl = 0;
        for (int i = tid; i < M_TOT / 4; i += 1024) {  // safe subset for all dtypes
            const unsigned int x = w[i];
            if (x > 1u) a = 1;
            if (x != 0u && x != 0x3F800000u) fl = 1;
        }
        if (a)  atomicExch(&f_not01, 1);
        if (fl) atomicExch(&f_notf, 1);
        __syncthreads();
        const int mode = (!f_not01) ? 0 : ((!f_notf) ? 1 : 2);
        if (tid < 32) {
            const int wrd = tid;
            unsigned int bits = 0;
#pragma unroll 4
            for (int i = 0; i < 32; ++i) {
                const int s = wrd * 32 + i;
                const int j = b * SS + s;              // mask is [B][S]
                int mv;
                if (mode == 0)      mv = ((const int*)mraw)[j] != 0;
                else if (mode == 1) mv = ((const unsigned int*)mraw)[j] != 0u;
                else                mv = ((const unsigned char*)mraw)[j] != 0;
                if (!mv) bits |= (1u << i);            // pad bit
            }
            g_padbits[b][wrd] = bits;
        }
    }
}

// ---------------------------------------------------------------------------
// Launch: prep_fused(0), then one fused layer kernel per layer (1..4).
// ---------------------------------------------------------------------------
extern "C" void kernel_launch(void* const* d_in, const int* in_sizes, int n_in,
                              void* d_out, int out_size) {
    const int*   ids  = (const int*)d_in[0];
    const void*  mask = d_in[1];
    const float* emb  = (const float*)d_in[2];
    const float* W    = (const float*)d_in[3];
    const float* v    = (const float*)d_in[4];
    const float* bias = (const float*)d_in[5];
    float* out = (float*)d_out;

    cudaFuncSetAttribute(sru_layer_kernel, cudaFuncAttributeMaxDynamicSharedMemorySize, LAYER_SMEM);

    sru_prep_fused<<<7200, 1024>>>(W, ids, emb, mask);                      // 0

    const int total_ctas = SCAN_CTAS + (N_TOT / BN) * (M_TOT / BM);         // 64 + 3072
    for (int l = 0; l < NL; ++l) {
        const int xin = l & 1;
        sru_layer_kernel<<<total_ctas, 256, LAYER_SMEM>>>(l, xin, v, bias, out,
                                                          (l == NL - 1) ? 1 : 0);  // 1..4
    }
}